// round 4
// baseline (speedup 1.0000x reference)
#include <cuda_runtime.h>
#include <math.h>

#define DDIM   512
#define KCODES 1024
#define BM 128
#define BN 128
#define BK 16
#define ASTR 132   // padded row stride (floats) for smem tiles

// ---- device-global scratch (allowed; no runtime allocation) ----
__device__ float        g_cnorm[KCODES];
__device__ unsigned int g_hist[KCODES];
__device__ double       g_sumsq;

// ============================================================
// Prep: codebook squared norms (double-accurate, f32 result) +
// zero accumulators (every launch; graph replays rerun sequence)
// ============================================================
__global__ void vq_prep(const float* __restrict__ cb) {
    int k = blockIdx.x;          // one block per code
    int t = threadIdx.x;         // 128 threads
    const float4* row = (const float4*)(cb + (size_t)k * DDIM);
    float4 q = row[t];           // 128 float4 = 512 floats
    // ref: fl(c*c) elementwise, then reduce; we reduce in double (<=0.5ulp)
    double v = (double)__fmul_rn(q.x,q.x) + (double)__fmul_rn(q.y,q.y)
             + (double)__fmul_rn(q.z,q.z) + (double)__fmul_rn(q.w,q.w);
    #pragma unroll
    for (int off = 16; off; off >>= 1) v += __shfl_down_sync(0xFFFFFFFFu, v, off);
    __shared__ double ws[4];
    if ((t & 31) == 0) ws[t >> 5] = v;
    __syncthreads();
    if (t == 0) {
        g_cnorm[k] = (float)(ws[0] + ws[1] + ws[2] + ws[3]);
        g_hist[k]  = 0u;
        if (k == 0) g_sumsq = 0.0;
    }
}

// ============================================================
// Main: fused SGEMM (ascending-k single-acc FMA chain == cublas) +
// reference-faithful score rounding + per-row argmin (first-index
// tie-break) + quantized write + loss partial + histogram.
// ============================================================
__global__ __launch_bounds__(256)
void vq_main(const float* __restrict__ in, const float* __restrict__ cb,
             float* __restrict__ out, int nrows) {
    __shared__ float As[BK * ASTR];      // [dd][row]  (transposed)
    __shared__ float Bs[BK * ASTR];      // [dd][col]
    __shared__ float cn_s[KCODES];
    __shared__ float rs_s[BM];
    __shared__ int   idx_s[BM];
    __shared__ float red_s[8];

    const int tid = threadIdx.x;
    const int tx  = tid & 15;            // 0..15 -> 8 cols each
    const int ty  = tid >> 4;            // 0..15 -> 8 rows each
    const int rowBase = blockIdx.x * BM;

    for (int i = tid; i < KCODES; i += 256) cn_s[i] = g_cnorm[i];

    // per-row squared norms, double-accurate then rounded to f32.
    // (whole-ulp deviations vs ref's own f32 reduction shift the whole
    //  row's score lattice uniformly -> argmin invariant)
    if (tid < BM) {
        const float4* rp = (const float4*)(in + (size_t)(rowBase + tid) * DDIM);
        double s = 0.0;
        #pragma unroll 8
        for (int i = 0; i < DDIM / 4; i++) {
            float4 v = rp[i];
            s += (double)__fmul_rn(v.x,v.x) + (double)__fmul_rn(v.y,v.y)
               + (double)__fmul_rn(v.z,v.z) + (double)__fmul_rn(v.w,v.w);
        }
        rs_s[tid] = (float)s;
    }
    __syncthreads();

    float bestV[8];
    int   bestI[8];
    #pragma unroll
    for (int i = 0; i < 8; i++) { bestV[i] = 3.4e38f; bestI[i] = 0x7FFFFFFF; }

    for (int kc0 = 0; kc0 < KCODES; kc0 += BN) {
        float acc[8][8];
        #pragma unroll
        for (int i = 0; i < 8; i++)
            #pragma unroll
            for (int j = 0; j < 8; j++) acc[i][j] = 0.f;

        for (int d0 = 0; d0 < DDIM; d0 += BK) {
            // stage A (input rows) and B (codebook rows), transposed to [dd][m]
            #pragma unroll
            for (int p = 0; p < 2; p++) {
                int id = tid + p * 256;          // 0..511
                int r  = id >> 2;                // 0..127
                int c4 = id & 3;                 // float4 slot within 16 d's
                float4 va = *(const float4*)(in + (size_t)(rowBase + r) * DDIM + d0 + c4 * 4);
                As[(c4*4+0)*ASTR + r] = va.x;
                As[(c4*4+1)*ASTR + r] = va.y;
                As[(c4*4+2)*ASTR + r] = va.z;
                As[(c4*4+3)*ASTR + r] = va.w;
                float4 vb = *(const float4*)(cb + (size_t)(kc0 + r) * DDIM + d0 + c4 * 4);
                Bs[(c4*4+0)*ASTR + r] = vb.x;
                Bs[(c4*4+1)*ASTR + r] = vb.y;
                Bs[(c4*4+2)*ASTR + r] = vb.z;
                Bs[(c4*4+3)*ASTR + r] = vb.w;
            }
            __syncthreads();
            // strictly ascending k, one accumulator per output element:
            // identical rounding chain to cublas/Eigen SGEMM.
            #pragma unroll
            for (int kk = 0; kk < BK; kk++) {
                float4 a0 = *(const float4*)&As[kk*ASTR + ty*8];
                float4 a1 = *(const float4*)&As[kk*ASTR + ty*8 + 4];
                float4 b0 = *(const float4*)&Bs[kk*ASTR + tx*8];
                float4 b1 = *(const float4*)&Bs[kk*ASTR + tx*8 + 4];
                float a[8] = {a0.x,a0.y,a0.z,a0.w,a1.x,a1.y,a1.z,a1.w};
                float b[8] = {b0.x,b0.y,b0.z,b0.w,b1.x,b1.y,b1.z,b1.w};
                #pragma unroll
                for (int i = 0; i < 8; i++)
                    #pragma unroll
                    for (int j = 0; j < 8; j++)
                        acc[i][j] = fmaf(a[i], b[j], acc[i][j]);
            }
            __syncthreads();
        }

        // Reference-faithful score: fl(fl(rs + cn) - 2*m), NO fma contraction.
        // Ascending column order + strict '<' => first index on ties,
        // matching jnp.argmin on the same rounded lattice values.
        #pragma unroll
        for (int i = 0; i < 8; i++) {
            float rsv = rs_s[ty * 8 + i];
            float bv = 3.4e38f; int bi = 0x7FFFFFFF;
            #pragma unroll
            for (int j = 0; j < 8; j++) {
                int col = kc0 + tx * 8 + j;
                float s = __fsub_rn(__fadd_rn(rsv, cn_s[col]),
                                    __fmul_rn(2.0f, acc[i][j]));
                if (s < bv) { bv = s; bi = col; }
            }
            #pragma unroll
            for (int off = 1; off < 16; off <<= 1) {
                float ov = __shfl_xor_sync(0xFFFFFFFFu, bv, off);
                int   oi = __shfl_xor_sync(0xFFFFFFFFu, bi, off);
                if (ov < bv || (ov == bv && oi < bi)) { bv = ov; bi = oi; }
            }
            if (bv < bestV[i] || (bv == bestV[i] && bi < bestI[i])) {
                bestV[i] = bv; bestI[i] = bi;
            }
        }
    }

    if (tx == 0) {
        #pragma unroll
        for (int i = 0; i < 8; i++) idx_s[ty * 8 + i] = bestI[i];
    }
    __syncthreads();

    if (tid < BM) atomicAdd(&g_hist[idx_s[tid]], 1u);

    // quantized write (d_out+1 is only 4B-aligned -> scalar, coalesced)
    // + loss partial sum
    float local = 0.f;
    #pragma unroll 4
    for (int e = tid; e < BM * DDIM; e += 256) {
        int r = e >> 9;           // /512
        int c = e & 511;
        int idx = idx_s[r];
        float q = cb[(size_t)idx * DDIM + c];
        float x = in[(size_t)(rowBase + r) * DDIM + c];
        out[1 + (size_t)(rowBase + r) * DDIM + c] = q;
        float d = q - x;
        local = fmaf(d, d, local);
    }
    #pragma unroll
    for (int off = 16; off; off >>= 1) local += __shfl_down_sync(0xFFFFFFFFu, local, off);
    if ((tid & 31) == 0) red_s[tid >> 5] = local;
    __syncthreads();
    if (tid == 0) {
        float s = 0.f;
        #pragma unroll
        for (int w = 0; w < 8; w++) s += red_s[w];
        atomicAdd(&g_sumsq, (double)s);
    }
}

// ============================================================
// Finalize: loss + perplexity scalars
// ============================================================
__global__ void vq_final(float* __restrict__ out, int out_size, int nrows) {
    int t = threadIdx.x;                 // 1024 == KCODES
    double p = (double)g_hist[t] / (double)nrows;
    double term = p * log(p + 1e-10);
    #pragma unroll
    for (int off = 16; off; off >>= 1) term += __shfl_down_sync(0xFFFFFFFFu, term, off);
    __shared__ double ws[32];
    if ((t & 31) == 0) ws[t >> 5] = term;
    __syncthreads();
    if (t == 0) {
        double s = 0.0;
        #pragma unroll
        for (int w = 0; w < 32; w++) s += ws[w];
        double mean = g_sumsq / ((double)nrows * (double)DDIM);
        out[0] = (float)(1.25 * mean);            // q_loss + 0.25*e_loss
        out[out_size - 1] = (float)exp(-s);       // perplexity
    }
}

// ============================================================
extern "C" void kernel_launch(void* const* d_in, const int* in_sizes, int n_in,
                              void* d_out, int out_size) {
    const float* inputs = (const float*)d_in[0];
    const float* cb     = (const float*)d_in[1];
    float* out = (float*)d_out;
    int nrows = in_sizes[0] / DDIM;      // 65536

    vq_prep<<<KCODES, 128>>>(cb);
    vq_main<<<nrows / BM, 256>>>(inputs, cb, out, nrows);
    vq_final<<<1, KCODES>>>(out, out_size, nrows);
}

// round 6
// speedup vs baseline: 1.6928x; 1.6928x over previous
#include <cuda_runtime.h>
#include <cuda_fp16.h>
#include <math.h>

#define DDIM 512
#define KCODES 1024
#define NR 65536
#define BM 128
#define BN 128
#define BK 16
#define NCH (DDIM/BK)        // 32
#define NSWEEP (KCODES/BN)   // 8

// dynamic smem layout (bytes)
#define OFF_CN  0
#define OFF_IDX 4096
#define OFF_RV  4608
#define OFF_RI  6656
#define OFF_A   8704
#define ATILE   6144         // 128 rows * 48B (stride 24 halfs)
#define ABUF    (2*ATILE)    // hi + lo
#define OFF_B   (OFF_A + 2*ABUF)
#define SMEM_TOTAL (OFF_B + 2*ABUF)   // 57856

__device__ float        g_cnorm[KCODES];
__device__ float        g_rnorm[NR];
__device__ unsigned int g_hist[KCODES];
__device__ double       g_sumsq;
__device__ __half       g_Bh[KCODES * DDIM];
__device__ __half       g_Bl[KCODES * DDIM];

// ---------------- helpers ----------------
__device__ __forceinline__ unsigned smem_u32(const void* p) {
    unsigned a;
    asm("{ .reg .u64 t; cvta.to.shared.u64 t, %1; cvt.u32.u64 %0, t; }" : "=r"(a) : "l"(p));
    return a;
}
__device__ __forceinline__ void ldsm4(unsigned* r, unsigned a) {
    asm volatile("ldmatrix.sync.aligned.m8n8.x4.shared.b16 {%0,%1,%2,%3}, [%4];"
        : "=r"(r[0]), "=r"(r[1]), "=r"(r[2]), "=r"(r[3]) : "r"(a));
}
__device__ __forceinline__ void ldsm2(unsigned* r, unsigned a) {
    asm volatile("ldmatrix.sync.aligned.m8n8.x2.shared.b16 {%0,%1}, [%2];"
        : "=r"(r[0]), "=r"(r[1]) : "r"(a));
}
__device__ __forceinline__ void mma16816(float* d, const unsigned* a, const unsigned* b) {
    asm volatile("mma.sync.aligned.m16n8k16.row.col.f32.f16.f16.f32 "
        "{%0,%1,%2,%3}, {%4,%5,%6,%7}, {%8,%9}, {%0,%1,%2,%3};"
        : "+f"(d[0]), "+f"(d[1]), "+f"(d[2]), "+f"(d[3])
        : "r"(a[0]), "r"(a[1]), "r"(a[2]), "r"(a[3]), "r"(b[0]), "r"(b[1]));
}
// split 8 f32 -> hi/lo f16 packs (lo pre-scaled by 2^11)
__device__ __forceinline__ void split8(float4 x0, float4 x1, uint4& uh, uint4& ul) {
    float xs[8] = {x0.x, x0.y, x0.z, x0.w, x1.x, x1.y, x1.z, x1.w};
    unsigned hs[8], ls[8];
    #pragma unroll
    for (int j = 0; j < 8; j++) {
        __half a = __float2half_rn(xs[j]);
        float  r = __fsub_rn(xs[j], __half2float(a));
        __half l = __float2half_rn(__fmul_rn(r, 2048.0f));
        hs[j] = __half_as_ushort(a); ls[j] = __half_as_ushort(l);
    }
    uh.x = hs[0] | (hs[1] << 16); uh.y = hs[2] | (hs[3] << 16);
    uh.z = hs[4] | (hs[5] << 16); uh.w = hs[6] | (hs[7] << 16);
    ul.x = ls[0] | (ls[1] << 16); ul.y = ls[2] | (ls[3] << 16);
    ul.z = ls[4] | (ls[5] << 16); ul.w = ls[6] | (ls[7] << 16);
}

// ---------------- prep: codebook norms + f16 split + zero accum ----------------
__global__ void vq_prep_cb(const float* __restrict__ cb) {
    int k = blockIdx.x, t = threadIdx.x;                    // 128 threads
    float4 q = ((const float4*)(cb + (size_t)k * DDIM))[t];
    double v = (double)__fmul_rn(q.x, q.x) + (double)__fmul_rn(q.y, q.y)
             + (double)__fmul_rn(q.z, q.z) + (double)__fmul_rn(q.w, q.w);
    #pragma unroll
    for (int o = 16; o; o >>= 1) v += __shfl_down_sync(0xFFFFFFFFu, v, o);
    __shared__ double ws[4];
    if ((t & 31) == 0) ws[t >> 5] = v;
    float xs[4] = {q.x, q.y, q.z, q.w};
    unsigned hs[4], ls[4];
    #pragma unroll
    for (int j = 0; j < 4; j++) {
        __half a = __float2half_rn(xs[j]);
        float  r = __fsub_rn(xs[j], __half2float(a));
        __half l = __float2half_rn(__fmul_rn(r, 2048.0f));
        hs[j] = __half_as_ushort(a); ls[j] = __half_as_ushort(l);
    }
    uint2 uh = {hs[0] | (hs[1] << 16), hs[2] | (hs[3] << 16)};
    uint2 ul = {ls[0] | (ls[1] << 16), ls[2] | (ls[3] << 16)};
    ((uint2*)(g_Bh + (size_t)k * DDIM))[t] = uh;
    ((uint2*)(g_Bl + (size_t)k * DDIM))[t] = ul;
    __syncthreads();
    if (t == 0) {
        g_cnorm[k] = (float)(ws[0] + ws[1] + ws[2] + ws[3]);
        g_hist[k] = 0u;
        if (k == 0) g_sumsq = 0.0;
    }
}

// ---------------- prep: per-row squared norms ----------------
__global__ void vq_prep_rows(const float* __restrict__ in) {
    int wid = threadIdx.x >> 5, lid = threadIdx.x & 31;
    int row = blockIdx.x * 8 + wid;
    const float4* rp = (const float4*)(in + (size_t)row * DDIM);
    double s = 0.0;
    #pragma unroll
    for (int i = 0; i < 4; i++) {
        float4 v = rp[lid + i * 32];
        s += (double)__fmul_rn(v.x, v.x) + (double)__fmul_rn(v.y, v.y)
           + (double)__fmul_rn(v.z, v.z) + (double)__fmul_rn(v.w, v.w);
    }
    #pragma unroll
    for (int o = 16; o; o >>= 1) s += __shfl_down_sync(0xFFFFFFFFu, s, o);
    if (lid == 0) g_rnorm[row] = (float)s;
}

// ---------------- main: HMMA split-f16 GEMM + argmin + outputs ----------------
__global__ void __launch_bounds__(256, 1)
vq_main(const float* __restrict__ in, const float* __restrict__ cb,
        float* __restrict__ out) {
    extern __shared__ char smem[];
    const unsigned sb = smem_u32(smem);
    float* cn_s = (float*)(smem + OFF_CN);
    const int tid = threadIdx.x, l = tid & 31, wid = tid >> 5;
    const int wm = wid >> 2, wn = wid & 3;            // 2m x 4n warp grid
    const int rowBase = blockIdx.x * BM;

    for (int i = tid; i < KCODES; i += 256) cn_s[i] = g_cnorm[i];

    // per-lane row norms for the 8 (mt,half) slots
    float rsv[8];
    #pragma unroll
    for (int s = 0; s < 8; s++)
        rsv[s] = g_rnorm[rowBase + wm * 64 + (s >> 1) * 16 + (s & 1) * 8 + (l >> 2)];

    // ldmatrix lane addressing
    const unsigned aRB = (l & 15) * 48 + (l >> 4) * 16;
    const unsigned bRB = (l & 7) * 48 + ((l >> 3) & 1) * 16;
    // global load mapping: row, 8-float segment
    const int ldr = tid >> 1, seg = tid & 1;
    const unsigned aSto = ldr * 48 + seg * 16;

    float bestV[8]; int bestI[8];
    #pragma unroll
    for (int s = 0; s < 8; s++) { bestV[s] = 3.4e38f; bestI[s] = 0x7FFFFFFF; }

    __syncthreads();

    for (int sw = 0; sw < NSWEEP; sw++) {
        const int kc0 = sw * BN;
        float D0[4][4][4], D1[4][4][4];
        #pragma unroll
        for (int mt = 0; mt < 4; mt++)
            #pragma unroll
            for (int nt = 0; nt < 4; nt++)
                #pragma unroll
                for (int e = 0; e < 4; e++) { D0[mt][nt][e] = 0.f; D1[mt][nt][e] = 0.f; }

        // prologue: chunk 0 -> buf 0
        {
            const float4* ga = (const float4*)(in + (size_t)(rowBase + ldr) * DDIM + seg * 8);
            float4 a0 = ga[0], a1 = ga[1];
            uint4 uh, ul; split8(a0, a1, uh, ul);
            *(uint4*)(smem + OFF_A + aSto) = uh;
            *(uint4*)(smem + OFF_A + ATILE + aSto) = ul;
            *(uint4*)(smem + OFF_B + aSto) =
                *(const uint4*)(g_Bh + (size_t)(kc0 + ldr) * DDIM + seg * 8);
            *(uint4*)(smem + OFF_B + ATILE + aSto) =
                *(const uint4*)(g_Bl + (size_t)(kc0 + ldr) * DDIM + seg * 8);
        }

        for (int c = 0; c < NCH; c++) {
            __syncthreads();                       // buf[c&1] ready for all
            const int buf = c & 1;
            float4 pa0, pa1; uint4 pbh, pbl;
            if (c + 1 < NCH) {                     // prefetch next chunk
                int d0 = (c + 1) * BK;
                const float4* ga = (const float4*)(in + (size_t)(rowBase + ldr) * DDIM + d0 + seg * 8);
                pa0 = ga[0]; pa1 = ga[1];
                pbh = *(const uint4*)(g_Bh + (size_t)(kc0 + ldr) * DDIM + d0 + seg * 8);
                pbl = *(const uint4*)(g_Bl + (size_t)(kc0 + ldr) * DDIM + d0 + seg * 8);
            }
            // fragments
            const unsigned SAh = sb + OFF_A + buf * ABUF, SAl = SAh + ATILE;
            const unsigned SBh = sb + OFF_B + buf * ABUF, SBl = SBh + ATILE;
            unsigned ah[4][4], al[4][4], bh[4][2], bl[4][2];
            #pragma unroll
            for (int mt = 0; mt < 4; mt++) {
                unsigned r0 = (wm * 64 + mt * 16) * 48 + aRB;
                ldsm4(ah[mt], SAh + r0);
                ldsm4(al[mt], SAl + r0);
            }
            #pragma unroll
            for (int nt = 0; nt < 4; nt++) {
                unsigned r0 = (wn * 32 + nt * 8) * 48 + bRB;
                ldsm2(bh[nt], SBh + r0);
                ldsm2(bl[nt], SBl + r0);
            }
            #pragma unroll
            for (int mt = 0; mt < 4; mt++)
                #pragma unroll
                for (int nt = 0; nt < 4; nt++) {
                    mma16816(D0[mt][nt], ah[mt], bh[nt]);
                    mma16816(D1[mt][nt], ah[mt], bl[nt]);
                    mma16816(D1[mt][nt], al[mt], bh[nt]);
                }
            if (c + 1 < NCH) {                     // stage next chunk -> other buf
                uint4 uh, ul; split8(pa0, pa1, uh, ul);
                char* dst = smem + (buf ^ 1) * ABUF;
                *(uint4*)(dst + OFF_A + aSto) = uh;
                *(uint4*)(dst + OFF_A + ATILE + aSto) = ul;
                *(uint4*)(dst + OFF_B + aSto) = pbh;
                *(uint4*)(dst + OFF_B + ATILE + aSto) = pbl;
            }
        }

        // sweep epilogue: lattice scores + running argmin (registers only)
        #pragma unroll
        for (int mt = 0; mt < 4; mt++)
            #pragma unroll
            for (int nt = 0; nt < 4; nt++)
                #pragma unroll
                for (int e = 0; e < 4; e++) {
                    int slot = mt * 2 + (e >> 1);
                    int col = kc0 + wn * 32 + nt * 8 + (l & 3) * 2 + (e & 1);
                    float dot = __fmaf_rn(D1[mt][nt][e], 4.8828125e-4f, D0[mt][nt][e]);
                    float s = __fsub_rn(__fadd_rn(rsv[slot], cn_s[col]),
                                        __fadd_rn(dot, dot));
                    if (s < bestV[slot]) { bestV[slot] = s; bestI[slot] = col; }
                }
    }

    // cross-lane reduce (lanes xor 1,2 share identical row sets)
    #pragma unroll
    for (int s = 0; s < 8; s++)
        #pragma unroll
        for (int off = 1; off < 4; off <<= 1) {
            float ov = __shfl_xor_sync(0xFFFFFFFFu, bestV[s], off);
            int   oi = __shfl_xor_sync(0xFFFFFFFFu, bestI[s], off);
            if (ov < bestV[s] || (ov == bestV[s] && oi < bestI[s])) {
                bestV[s] = ov; bestI[s] = oi;
            }
        }
    float* rv = (float*)(smem + OFF_RV);
    int*   ri = (int*)(smem + OFF_RI);
    __syncthreads();                                // mainloop smem reads done
    if ((l & 3) == 0) {
        #pragma unroll
        for (int s = 0; s < 8; s++) {
            int row = wm * 64 + (s >> 1) * 16 + (s & 1) * 8 + (l >> 2);
            rv[row * 4 + wn] = bestV[s]; ri[row * 4 + wn] = bestI[s];
        }
    }
    __syncthreads();

    int* idx_s = (int*)(smem + OFF_IDX);
    __shared__ float red8[8];
    float lv = 0.f;
    if (tid < BM) {
        float bv = 3.4e38f; int bi = 0x7FFFFFFF;
        #pragma unroll
        for (int w = 0; w < 4; w++) {
            float v = rv[tid * 4 + w]; int i2 = ri[tid * 4 + w];
            if (v < bv || (v == bv && i2 < bi)) { bv = v; bi = i2; }
        }
        idx_s[tid] = bi;
        atomicAdd(&g_hist[bi], 1u);
        lv = bv;                                    // min score == ||x-c||^2
    }
    #pragma unroll
    for (int o = 16; o; o >>= 1) lv += __shfl_down_sync(0xFFFFFFFFu, lv, o);
    if ((tid & 31) == 0) red8[wid] = lv;
    __syncthreads();
    if (tid == 0) {
        float s = 0.f;
        #pragma unroll
        for (int w = 0; w < 8; w++) s += red8[w];
        atomicAdd(&g_sumsq, (double)s);
    }
    // gather-write quantized
    for (int e = tid; e < BM * DDIM; e += 256) {
        int rr = e >> 9, cc = e & 511;
        out[1 + (size_t)(rowBase + rr) * DDIM + cc] = cb[(size_t)idx_s[rr] * DDIM + cc];
    }
}

// ---------------- finalize scalars ----------------
__global__ void vq_final(float* __restrict__ out, int out_size) {
    int t = threadIdx.x;                            // 1024
    double p = (double)g_hist[t] / (double)NR;
    double term = p * log(p + 1e-10);
    #pragma unroll
    for (int o = 16; o; o >>= 1) term += __shfl_down_sync(0xFFFFFFFFu, term, o);
    __shared__ double ws[32];
    if ((t & 31) == 0) ws[t >> 5] = term;
    __syncthreads();
    if (t == 0) {
        double s = 0.0;
        #pragma unroll
        for (int w = 0; w < 32; w++) s += ws[w];
        double mean = g_sumsq / ((double)NR * (double)DDIM);
        out[0] = (float)(1.25 * mean);
        out[out_size - 1] = (float)exp(-s);
    }
}

extern "C" void kernel_launch(void* const* d_in, const int* in_sizes, int n_in,
                              void* d_out, int out_size) {
    const float* inputs = (const float*)d_in[0];
    const float* cb     = (const float*)d_in[1];
    float* out = (float*)d_out;
    int nrows = in_sizes[0] / DDIM;

    cudaFuncSetAttribute(vq_main, cudaFuncAttributeMaxDynamicSharedMemorySize, SMEM_TOTAL);
    vq_prep_cb<<<KCODES, 128>>>(cb);
    vq_prep_rows<<<nrows / 8, 256>>>(inputs);
    vq_main<<<nrows / BM, 256, SMEM_TOTAL>>>(inputs, cb, out);
    vq_final<<<1, KCODES>>>(out, out_size);
}